// round 1
// baseline (speedup 1.0000x reference)
#include <cuda_runtime.h>

#define NB 2
#define NN 20000
#define DD 256
#define EE 320000
#define NL 2
#define ALPHA 0.2f

// Scratch (device globals — no allocation allowed)
__device__ float g_h  [NB * NN * DD];   // h  = x  @ W_l
__device__ float g_hq [NB * NN * DD];   // hq = xq @ W_l
__device__ float g_cur[NB * NN * DD];   // layer input (after layer 0)
__device__ float g_agg[NB * NN * DD];   // segment-sum accumulator
__device__ float g_rowsum[NB * NN];
__device__ float g_sq[NB * NN];
__device__ float g_sn[NB * NN];

// ---------------------------------------------------------------------------
// GEMM: C[z] = A[z] @ W_l, A in {x_b or g_cur_b, xq_b}, 64x64x16 tile, fp32.
// grid: (ceil(N/64), D/64, 2*B); z = b*2 + which (which=1 -> hq path)
// ---------------------------------------------------------------------------
__global__ void gemm64(const float* __restrict__ X,
                       const float* __restrict__ XQ,
                       const float* __restrict__ Wl,
                       int use_cur)
{
    int z = blockIdx.z;
    int b = z >> 1;
    int which = z & 1;
    const float* A;
    if (which) A = XQ + (size_t)b * NN * DD;
    else       A = (use_cur ? g_cur : X) + (size_t)b * NN * DD;
    float* C = (which ? g_hq : g_h) + (size_t)b * NN * DD;

    __shared__ float As[16][64];   // transposed A tile
    __shared__ float Bs[16][64];

    int tid = threadIdx.x;           // 256 threads
    int row0 = blockIdx.x * 64;
    int col0 = blockIdx.y * 64;
    int ty = tid >> 4;               // 0..15
    int tx = tid & 15;               // 0..15

    int a_row = tid >> 2;            // 0..63
    int a_col = (tid & 3) * 4;       // 0,4,8,12
    int b_row = tid >> 4;            // 0..15
    int b_col = (tid & 15) * 4;      // 0..60

    float acc[4][4] = {};

    for (int k0 = 0; k0 < DD; k0 += 16) {
        float4 av = make_float4(0.f, 0.f, 0.f, 0.f);
        int grow = row0 + a_row;
        if (grow < NN)
            av = *(const float4*)(A + (size_t)grow * DD + k0 + a_col);
        As[a_col + 0][a_row] = av.x;
        As[a_col + 1][a_row] = av.y;
        As[a_col + 2][a_row] = av.z;
        As[a_col + 3][a_row] = av.w;

        float4 bv = *(const float4*)(Wl + (size_t)(k0 + b_row) * DD + col0 + b_col);
        *(float4*)&Bs[b_row][b_col] = bv;
        __syncthreads();

        #pragma unroll
        for (int k = 0; k < 16; k++) {
            float ra[4], rb[4];
            #pragma unroll
            for (int i = 0; i < 4; i++) ra[i] = As[k][ty * 4 + i];
            #pragma unroll
            for (int j = 0; j < 4; j++) rb[j] = Bs[k][tx * 4 + j];
            #pragma unroll
            for (int i = 0; i < 4; i++)
                #pragma unroll
                for (int j = 0; j < 4; j++)
                    acc[i][j] += ra[i] * rb[j];
        }
        __syncthreads();
    }

    #pragma unroll
    for (int i = 0; i < 4; i++) {
        int r = row0 + ty * 4 + i;
        if (r < NN) {
            float4 v = make_float4(acc[i][0], acc[i][1], acc[i][2], acc[i][3]);
            *(float4*)(C + (size_t)r * DD + col0 + tx * 4) = v;
        }
    }
}

// ---------------------------------------------------------------------------
// Per-node scores sq = hq·a[:D], sn = h·a[D:]; also zeroes agg row + rowsum.
// grid: B*N blocks, 256 threads.
// ---------------------------------------------------------------------------
__global__ void score_zero(const float* __restrict__ a_l)
{
    int node = blockIdx.x;
    int t = threadIdx.x;
    size_t base = (size_t)node * DD;

    float vq = g_hq[base + t] * a_l[t];
    float vn = g_h [base + t] * a_l[DD + t];

    #pragma unroll
    for (int o = 16; o > 0; o >>= 1) {
        vq += __shfl_down_sync(0xFFFFFFFFu, vq, o);
        vn += __shfl_down_sync(0xFFFFFFFFu, vn, o);
    }
    __shared__ float sqs[8], sns[8];
    int w = t >> 5, ln = t & 31;
    if (ln == 0) { sqs[w] = vq; sns[w] = vn; }
    __syncthreads();
    if (t == 0) {
        float S = 0.f, T = 0.f;
        #pragma unroll
        for (int i = 0; i < 8; i++) { S += sqs[i]; T += sns[i]; }
        g_sq[node] = S;
        g_sn[node] = T;
        g_rowsum[node] = 0.f;
    }
    g_agg[base + t] = 0.f;
}

// ---------------------------------------------------------------------------
// Edge kernel: one warp per edge. w = exp(-leakyrelu(sq[src]+sn[dst]));
// atomically: rowsum[src] += w; agg[src][:] += w * h[dst][:].
// ---------------------------------------------------------------------------
__global__ void edge_kernel(const int* __restrict__ edges)
{
    int gw = (int)((blockIdx.x * (size_t)blockDim.x + threadIdx.x) >> 5);
    int lane = threadIdx.x & 31;
    if (gw >= NB * EE) return;
    int b = gw / EE;
    int e = gw - b * EE;

    const int* eb = edges + (size_t)b * 2 * EE;
    int src = eb[e];
    int dst = eb[EE + e];

    float s = g_sq[b * NN + src] + g_sn[b * NN + dst];
    float lr = (s >= 0.f) ? s : ALPHA * s;
    float w = __expf(-lr);

    if (lane == 0)
        atomicAdd(&g_rowsum[b * NN + src], w);

    const float* hrow = g_h   + ((size_t)b * NN + dst) * DD;
    float*       arow = g_agg + ((size_t)b * NN + src) * DD;
    #pragma unroll
    for (int k = 0; k < 8; k++) {
        int d = lane + 32 * k;
        atomicAdd(&arow[d], w * hrow[d]);
    }
}

// ---------------------------------------------------------------------------
// Normalize; write next-layer input, or (last layer) out = h' + nodes.
// ---------------------------------------------------------------------------
__global__ void finalize(const float* __restrict__ nodes,
                         float* __restrict__ out, int last)
{
    int node = blockIdx.x;
    int t = threadIdx.x;
    size_t idx = (size_t)node * DD + t;
    float r = g_rowsum[node];
    float v = (r == 0.f) ? 0.f : g_agg[idx] / r;
    if (last) out[idx] = v + nodes[idx];
    else      g_cur[idx] = v;
}

// ---------------------------------------------------------------------------
extern "C" void kernel_launch(void* const* d_in, const int* in_sizes, int n_in,
                              void* d_out, int out_size)
{
    const float* nodes  = (const float*)d_in[0];
    const float* nodesq = (const float*)d_in[1];
    const float* W      = (const float*)d_in[2];   // [L, D, D]
    const float* a      = (const float*)d_in[3];   // [L, 2D]
    const int*   edges  = (const int*)d_in[4];     // [B, 2, E]
    float* out = (float*)d_out;

    dim3 ggrid((NN + 63) / 64, DD / 64, 2 * NB);
    int edge_blocks = (NB * EE * 32 + 255) / 256;

    for (int l = 0; l < NL; l++) {
        gemm64<<<ggrid, 256>>>(nodes, nodesq, W + (size_t)l * DD * DD, l > 0);
        score_zero<<<NB * NN, 256>>>(a + (size_t)l * 2 * DD);
        edge_kernel<<<edge_blocks, 256>>>(edges);
        finalize<<<NB * NN, 256>>>(nodes, out, l == NL - 1);
    }
}

// round 6
// speedup vs baseline: 1.5993x; 1.5993x over previous
#include <cuda_runtime.h>
#include <cuda_bf16.h>
#include <cstdint>

#define NB 2
#define NN 20000
#define DD 256
#define EE 320000
#define NL 2
#define ALPHA 0.2f

#define TM 128
#define TN 128
#define KC 32
#define NST (DD / KC)                 // 8
#define NTILES ((NN + TM - 1) / TM)   // 157
#define ROWB 80                       // 64B data + 16B pad
#define TILEB (128 * ROWB)            // 10240
#define SMEMB (4 * TILEB)             // 40960 (< 48KB)

// ---------------- device scratch ----------------
__device__ float g_h  [NB * NN * DD];
__device__ float g_cur[NB * NN * DD];
__device__ float g_agg[NB * NN * DD];
__device__ float g_rowsum[NB * NN];
__device__ float g_sq[NB * NN];
__device__ float g_sn[NB * NN];
__device__ float g_wa1[DD], g_wa2[DD];                   // W_l @ a1, W_l @ a2
__device__ __nv_bfloat16 g_wbh[DD * DD], g_wbl[DD * DD]; // W^T hi/lo, [n][k]

// ---------------- helpers ----------------
__device__ __forceinline__ uint32_t smem_u32(const void* p) {
    uint32_t a;
    asm("{ .reg .u64 t; cvta.to.shared.u64 t, %1; cvt.u32.u64 %0, t; }" : "=r"(a) : "l"(p));
    return a;
}
__device__ __forceinline__ void bf_split(float v, __nv_bfloat16& hi, __nv_bfloat16& lo) {
    hi = __float2bfloat16_rn(v);
    lo = __float2bfloat16_rn(v - __bfloat162float(hi));
}
__device__ __forceinline__ void ldx4(uint32_t r[4], uint32_t addr) {
    asm volatile("ldmatrix.sync.aligned.m8n8.x4.shared.b16 {%0,%1,%2,%3}, [%4];"
                 : "=r"(r[0]), "=r"(r[1]), "=r"(r[2]), "=r"(r[3]) : "r"(addr));
}
__device__ __forceinline__ void ldx2(uint32_t r[2], uint32_t addr) {
    asm volatile("ldmatrix.sync.aligned.m8n8.x2.shared.b16 {%0,%1}, [%2];"
                 : "=r"(r[0]), "=r"(r[1]) : "r"(addr));
}
__device__ __forceinline__ void mma16816(float c[4], const uint32_t a[4], const uint32_t b[2]) {
    asm volatile("mma.sync.aligned.m16n8k16.row.col.f32.bf16.bf16.f32 "
                 "{%0,%1,%2,%3}, {%4,%5,%6,%7}, {%8,%9}, {%0,%1,%2,%3};"
                 : "+f"(c[0]), "+f"(c[1]), "+f"(c[2]), "+f"(c[3])
                 : "r"(a[0]), "r"(a[1]), "r"(a[2]), "r"(a[3]), "r"(b[0]), "r"(b[1]));
}

// ---------------------------------------------------------------------------
// wa_kernel: g_wa1[k] = sum_n W[k][n] a[n],  g_wa2[k] = sum_n W[k][n] a[D+n]
// grid: DD blocks (one per k), 256 threads.
// ---------------------------------------------------------------------------
__global__ void wa_kernel(const float* __restrict__ Wl, const float* __restrict__ a_l) {
    int k = blockIdx.x, t = threadIdx.x;
    float w = Wl[k * DD + t];
    float v1 = w * a_l[t];
    float v2 = w * a_l[DD + t];
    #pragma unroll
    for (int o = 16; o > 0; o >>= 1) {
        v1 += __shfl_down_sync(0xFFFFFFFFu, v1, o);
        v2 += __shfl_down_sync(0xFFFFFFFFu, v2, o);
    }
    __shared__ float s1[8], s2[8];
    int wp = t >> 5, ln = t & 31;
    if (ln == 0) { s1[wp] = v1; s2[wp] = v2; }
    __syncthreads();
    if (t == 0) {
        float a1 = 0.f, a2 = 0.f;
        #pragma unroll
        for (int i = 0; i < 8; i++) { a1 += s1[i]; a2 += s2[i]; }
        g_wa1[k] = a1;
        g_wa2[k] = a2;
    }
}

// ---------------------------------------------------------------------------
// prep_w: W_l [k][n] -> g_wbh/g_wbl [n][k] bf16 hi/lo
// ---------------------------------------------------------------------------
__global__ void prep_w(const float* __restrict__ Wl) {
    int n = blockIdx.x, k = threadIdx.x;
    float v = Wl[k * DD + n];
    __nv_bfloat16 h, l;
    bf_split(v, h, l);
    g_wbh[n * DD + k] = h;
    g_wbl[n * DD + k] = l;
}

// ---------------------------------------------------------------------------
// HMMA bf16x3 GEMM: g_h[b] = X[b] @ W_l.  X fp32, split to hi/lo in staging.
// grid (NTILES, 2, NB), 256 threads, 40KB smem, synchronous staging.
// ---------------------------------------------------------------------------
__global__ void __launch_bounds__(256)
gemm_mma(const float* __restrict__ Xf) {
    extern __shared__ char smem[];
    const int tid = threadIdx.x;
    const int wid = tid >> 5, lane = tid & 31;
    const int wm = wid & 3, wn = wid >> 2;

    const int b = blockIdx.z;
    const size_t boff = (size_t)b * NN * DD;
    const float* A32 = Xf + boff;
    float* C = g_h + boff;
    const int row0 = blockIdx.x * TM;
    const int col0 = blockIdx.y * TN;

    const uint32_t sb = smem_u32(smem);

    float acc[2][8][4];
    #pragma unroll
    for (int i = 0; i < 2; i++)
        #pragma unroll
        for (int j = 0; j < 8; j++)
            #pragma unroll
            for (int q = 0; q < 4; q++) acc[i][j][q] = 0.f;

    const uint32_t aob = (uint32_t)((wm * 32 + (lane & 15)) * ROWB + (lane >> 4) * 16);
    const uint32_t bob = (uint32_t)((wn * 64 + (lane & 7)) * ROWB + ((lane >> 3) & 1) * 16);

    for (int c = 0; c < NST; c++) {
        const int k0 = c * KC;
        __syncthreads();
        // ---- stage A: fp32 -> bf16 hi/lo. 128 rows x 8 fp32-quarters ----
        #pragma unroll
        for (int s = 0; s < 4; s++) {
            int idx = tid + s * 256;          // 0..1023
            int row = idx >> 3;               // 0..127
            int q   = idx & 7;                // 16B fp32 quarter (4 floats)
            int agrow = row0 + row;
            float4 v = make_float4(0.f, 0.f, 0.f, 0.f);
            if (agrow < NN)
                v = *(const float4*)(A32 + (size_t)agrow * DD + k0 + q * 4);
            __nv_bfloat16 h[4], l[4];
            bf_split(v.x, h[0], l[0]); bf_split(v.y, h[1], l[1]);
            bf_split(v.z, h[2], l[2]); bf_split(v.w, h[3], l[3]);
            uint32_t so = (uint32_t)(row * ROWB + q * 8);
            *(uint2*)(smem + so)         = *(uint2*)h;
            *(uint2*)(smem + TILEB + so) = *(uint2*)l;
        }
        // ---- stage B: pre-split bf16 W^T. 128 rows x 4 16B-quarters ----
        #pragma unroll
        for (int s = 0; s < 2; s++) {
            int idx = tid + s * 256;          // 0..511
            int row = idx >> 2;               // n within tile
            int q   = idx & 3;
            uint32_t so = (uint32_t)(row * ROWB + q * 16);
            const size_t gb = (size_t)(col0 + row) * DD + k0 + q * 8;
            *(float4*)(smem + 2 * TILEB + so) = *(const float4*)(g_wbh + gb);
            *(float4*)(smem + 3 * TILEB + so) = *(const float4*)(g_wbl + gb);
        }
        __syncthreads();

        #pragma unroll
        for (int ks = 0; ks < 2; ks++) {
            uint32_t ao = sb + aob + ks * 32;
            uint32_t bo = sb + bob + ks * 32;
            uint32_t ahi[2][4], alo[2][4];
            #pragma unroll
            for (int mt = 0; mt < 2; mt++) {
                ldx4(ahi[mt], ao + mt * 16 * ROWB);
                ldx4(alo[mt], TILEB + ao + mt * 16 * ROWB);
            }
            #pragma unroll
            for (int nt = 0; nt < 8; nt++) {
                uint32_t bh[2], bl[2];
                ldx2(bh, 2 * TILEB + bo + nt * 8 * ROWB);
                ldx2(bl, 3 * TILEB + bo + nt * 8 * ROWB);
                #pragma unroll
                for (int mt = 0; mt < 2; mt++) {
                    mma16816(acc[mt][nt], ahi[mt], bh);
                    mma16816(acc[mt][nt], ahi[mt], bl);
                    mma16816(acc[mt][nt], alo[mt], bh);
                }
            }
        }
    }

    const int g = lane >> 2, t2 = (lane & 3) * 2;
    #pragma unroll
    for (int mt = 0; mt < 2; mt++) {
        int r = row0 + wm * 32 + mt * 16 + g;
        #pragma unroll
        for (int nt = 0; nt < 8; nt++) {
            int col = col0 + wn * 64 + nt * 8 + t2;
            if (r < NN)
                *(float2*)(C + (size_t)r * DD + col) = make_float2(acc[mt][nt][0], acc[mt][nt][1]);
            if (r + 8 < NN)
                *(float2*)(C + (size_t)(r + 8) * DD + col) = make_float2(acc[mt][nt][2], acc[mt][nt][3]);
        }
    }
}

// ---------------------------------------------------------------------------
// score_zero: EXACT fp32 scores from original inputs:
//   sq[n] = xq[n] . wa1,  sn[n] = xin[n] . wa2.  Also zero rowsum + agg.
// ---------------------------------------------------------------------------
__global__ void score_zero(const float* __restrict__ xq, const float* __restrict__ xin) {
    int node = blockIdx.x;
    int t = threadIdx.x;
    size_t idx = (size_t)node * DD + t;

    float vq = xq[idx]  * g_wa1[t];
    float vn = xin[idx] * g_wa2[t];
    #pragma unroll
    for (int o = 16; o > 0; o >>= 1) {
        vq += __shfl_down_sync(0xFFFFFFFFu, vq, o);
        vn += __shfl_down_sync(0xFFFFFFFFu, vn, o);
    }
    __shared__ float sqs[8], sns[8];
    int w = t >> 5, ln = t & 31;
    if (ln == 0) { sqs[w] = vq; sns[w] = vn; }
    __syncthreads();
    if (t == 0) {
        float S = 0.f, T = 0.f;
        #pragma unroll
        for (int i = 0; i < 8; i++) { S += sqs[i]; T += sns[i]; }
        g_sq[node] = S;
        g_sn[node] = T;
        g_rowsum[node] = 0.f;
    }
    g_agg[idx] = 0.f;
}

// ---------------------------------------------------------------------------
// Edge kernel: warp per edge, atomics into agg[src]
// ---------------------------------------------------------------------------
__global__ void edge_kernel(const int* __restrict__ edges) {
    int gw = (int)((blockIdx.x * (size_t)blockDim.x + threadIdx.x) >> 5);
    int lane = threadIdx.x & 31;
    if (gw >= NB * EE) return;
    int b = gw / EE;
    int e = gw - b * EE;

    const int* eb = edges + (size_t)b * 2 * EE;
    int src = eb[e];
    int dst = eb[EE + e];

    float s = g_sq[b * NN + src] + g_sn[b * NN + dst];
    float lr = (s >= 0.f) ? s : ALPHA * s;
    float w = __expf(-lr);

    if (lane == 0)
        atomicAdd(&g_rowsum[b * NN + src], w);

    const float* hrow = g_h   + ((size_t)b * NN + dst) * DD;
    float*       arow = g_agg + ((size_t)b * NN + src) * DD;
    #pragma unroll
    for (int k = 0; k < 8; k++) {
        int d = lane + 32 * k;
        atomicAdd(&arow[d], w * hrow[d]);
    }
}

// ---------------------------------------------------------------------------
// finalize: h' = agg/rowsum (0 if rowsum==0); fp32 next-layer input or output.
// ---------------------------------------------------------------------------
__global__ void finalize(const float* __restrict__ nodes,
                         float* __restrict__ out, int last) {
    int node = blockIdx.x;
    int t = threadIdx.x;
    size_t idx = (size_t)node * DD + t;
    float r = g_rowsum[node];
    float v = (r == 0.f) ? 0.f : g_agg[idx] / r;
    if (last) out[idx] = v + nodes[idx];
    else      g_cur[idx] = v;
}

// ---------------------------------------------------------------------------
extern "C" void kernel_launch(void* const* d_in, const int* in_sizes, int n_in,
                              void* d_out, int out_size) {
    const float* nodes  = (const float*)d_in[0];
    const float* nodesq = (const float*)d_in[1];
    const float* W      = (const float*)d_in[2];
    const float* a      = (const float*)d_in[3];
    const int*   edges  = (const int*)d_in[4];
    float* out = (float*)d_out;

    dim3 ggrid(NTILES, DD / TN, NB);
    int edge_blocks = (NB * EE * 32 + 255) / 256;

    for (int l = 0; l < NL; l++) {
        const float* Wl = W + (size_t)l * DD * DD;
        const float* xin_dev = nullptr;  // device pointers resolved below
        wa_kernel<<<DD, DD>>>(Wl, a + (size_t)l * 2 * DD);
        prep_w<<<DD, DD>>>(Wl);
        if (l == 0) {
            gemm_mma<<<ggrid, 256, SMEMB>>>(nodes);
            score_zero<<<NB * NN, 256>>>(nodesq, nodes);
        } else {
            float* curp = nullptr;
            cudaGetSymbolAddress((void**)&curp, g_cur);
            gemm_mma<<<ggrid, 256, SMEMB>>>(curp);
            score_zero<<<NB * NN, 256>>>(nodesq, curp);
        }
        (void)xin_dev;
        edge_kernel<<<edge_blocks, 256>>>(edges);
        finalize<<<NB * NN, 256>>>(nodes, out, l == NL - 1);
    }
}

// round 7
// speedup vs baseline: 2.0986x; 1.3123x over previous
#include <cuda_runtime.h>
#include <cuda_bf16.h>
#include <cstdint>

#define NB 2
#define NN 20000
#define DD 256
#define EE 320000
#define NL 2
#define ALPHA 0.2f

#define TM 128
#define TN 128
#define KC 32
#define NST (DD / KC)                 // 8
#define NTILES ((NN + TM - 1) / TM)   // 157
#define ROWB 80                       // 64B data + 16B pad
#define TILEB (128 * ROWB)            // 10240
#define SMEMB (4 * TILEB)             // 40960 (< 48KB)
#define NNODES (NB * NN)              // 40000
#define NEDGES (NB * EE)              // 640000

// ---------------- device scratch ----------------
__device__ float g_h  [NB * NN * DD];
__device__ float g_cur[NB * NN * DD];
__device__ float g_sq[NNODES];
__device__ float g_sn[NNODES];
__device__ float g_wa1[DD], g_wa2[DD];
__device__ __nv_bfloat16 g_wbh[DD * DD], g_wbl[DD * DD]; // W^T hi/lo, [n][k]
// CSR (built once per launch; edges are launch-invariant)
__device__ int g_deg [NNODES];
__device__ int g_eoff[NNODES + 1];
__device__ int g_ecur[NNODES];
__device__ int g_edst[NEDGES];

// ---------------- helpers ----------------
__device__ __forceinline__ uint32_t smem_u32(const void* p) {
    uint32_t a;
    asm("{ .reg .u64 t; cvta.to.shared.u64 t, %1; cvt.u32.u64 %0, t; }" : "=r"(a) : "l"(p));
    return a;
}
__device__ __forceinline__ void bf_split(float v, __nv_bfloat16& hi, __nv_bfloat16& lo) {
    hi = __float2bfloat16_rn(v);
    lo = __float2bfloat16_rn(v - __bfloat162float(hi));
}
__device__ __forceinline__ void ldx4(uint32_t r[4], uint32_t addr) {
    asm volatile("ldmatrix.sync.aligned.m8n8.x4.shared.b16 {%0,%1,%2,%3}, [%4];"
                 : "=r"(r[0]), "=r"(r[1]), "=r"(r[2]), "=r"(r[3]) : "r"(addr));
}
__device__ __forceinline__ void ldx2(uint32_t r[2], uint32_t addr) {
    asm volatile("ldmatrix.sync.aligned.m8n8.x2.shared.b16 {%0,%1}, [%2];"
                 : "=r"(r[0]), "=r"(r[1]) : "r"(addr));
}
__device__ __forceinline__ void mma16816(float c[4], const uint32_t a[4], const uint32_t b[2]) {
    asm volatile("mma.sync.aligned.m16n8k16.row.col.f32.bf16.bf16.f32 "
                 "{%0,%1,%2,%3}, {%4,%5,%6,%7}, {%8,%9}, {%0,%1,%2,%3};"
                 : "+f"(c[0]), "+f"(c[1]), "+f"(c[2]), "+f"(c[3])
                 : "r"(a[0]), "r"(a[1]), "r"(a[2]), "r"(a[3]), "r"(b[0]), "r"(b[1]));
}

// ============================ CSR construction ============================
__global__ void zero_deg() {
    int i = blockIdx.x * blockDim.x + threadIdx.x;
    if (i < NNODES) g_deg[i] = 0;
}
__global__ void hist(const int* __restrict__ edges) {
    int i = blockIdx.x * blockDim.x + threadIdx.x;
    if (i >= NEDGES) return;
    int b = i / EE, e = i - b * EE;
    int src = edges[(size_t)b * 2 * EE + e];
    atomicAdd(&g_deg[b * NN + src], 1);
}
// single-block inclusive-scan over 40k counters -> exclusive offsets
__global__ void scan_deg() {
    __shared__ int s[1024];
    int carry = 0;
    for (int base = 0; base < NNODES; base += 1024) {
        int i = base + threadIdx.x;
        s[threadIdx.x] = (i < NNODES) ? g_deg[i] : 0;
        __syncthreads();
        #pragma unroll
        for (int o = 1; o < 1024; o <<= 1) {
            int add = (threadIdx.x >= o) ? s[threadIdx.x - o] : 0;
            __syncthreads();
            s[threadIdx.x] += add;
            __syncthreads();
        }
        if (i < NNODES) g_eoff[i + 1] = carry + s[threadIdx.x];
        if (base == 0 && threadIdx.x == 0) g_eoff[0] = 0;
        carry += s[1023];
        __syncthreads();
    }
}
__global__ void copy_cur() {
    int i = blockIdx.x * blockDim.x + threadIdx.x;
    if (i < NNODES) g_ecur[i] = g_eoff[i];
}
__global__ void scatter(const int* __restrict__ edges) {
    int i = blockIdx.x * blockDim.x + threadIdx.x;
    if (i >= NEDGES) return;
    int b = i / EE, e = i - b * EE;
    const int* eb = edges + (size_t)b * 2 * EE;
    int src = eb[e], dst = eb[EE + e];
    int pos = atomicAdd(&g_ecur[b * NN + src], 1);
    g_edst[pos] = dst;
}

// ============================ per-layer kernels ============================
// wa: g_wa1[k] = sum_n W[k][n] a[n];  g_wa2[k] = sum_n W[k][n] a[D+n]
__global__ void wa_kernel(const float* __restrict__ Wl, const float* __restrict__ a_l) {
    int k = blockIdx.x, t = threadIdx.x;
    float w = Wl[k * DD + t];
    float v1 = w * a_l[t];
    float v2 = w * a_l[DD + t];
    #pragma unroll
    for (int o = 16; o > 0; o >>= 1) {
        v1 += __shfl_down_sync(0xFFFFFFFFu, v1, o);
        v2 += __shfl_down_sync(0xFFFFFFFFu, v2, o);
    }
    __shared__ float s1[8], s2[8];
    int wp = t >> 5, ln = t & 31;
    if (ln == 0) { s1[wp] = v1; s2[wp] = v2; }
    __syncthreads();
    if (t == 0) {
        float a1 = 0.f, a2 = 0.f;
        #pragma unroll
        for (int i = 0; i < 8; i++) { a1 += s1[i]; a2 += s2[i]; }
        g_wa1[k] = a1;
        g_wa2[k] = a2;
    }
}

__global__ void prep_w(const float* __restrict__ Wl) {
    int n = blockIdx.x, k = threadIdx.x;
    float v = Wl[k * DD + n];
    __nv_bfloat16 h, l;
    bf_split(v, h, l);
    g_wbh[n * DD + k] = h;
    g_wbl[n * DD + k] = l;
}

// HMMA bf16x3 GEMM: g_h[b] = X[b] @ W_l (fp32 in, hi/lo split in staging)
__global__ void __launch_bounds__(256)
gemm_mma(const float* __restrict__ Xf) {
    extern __shared__ char smem[];
    const int tid = threadIdx.x;
    const int wid = tid >> 5, lane = tid & 31;
    const int wm = wid & 3, wn = wid >> 2;

    const int b = blockIdx.z;
    const size_t boff = (size_t)b * NN * DD;
    const float* A32 = Xf + boff;
    float* C = g_h + boff;
    const int row0 = blockIdx.x * TM;
    const int col0 = blockIdx.y * TN;

    const uint32_t sb = smem_u32(smem);

    float acc[2][8][4];
    #pragma unroll
    for (int i = 0; i < 2; i++)
        #pragma unroll
        for (int j = 0; j < 8; j++)
            #pragma unroll
            for (int q = 0; q < 4; q++) acc[i][j][q] = 0.f;

    const uint32_t aob = (uint32_t)((wm * 32 + (lane & 15)) * ROWB + (lane >> 4) * 16);
    const uint32_t bob = (uint32_t)((wn * 64 + (lane & 7)) * ROWB + ((lane >> 3) & 1) * 16);

    for (int c = 0; c < NST; c++) {
        const int k0 = c * KC;
        __syncthreads();
        #pragma unroll
        for (int s = 0; s < 4; s++) {
            int idx = tid + s * 256;
            int row = idx >> 3;
            int q   = idx & 7;
            int agrow = row0 + row;
            float4 v = make_float4(0.f, 0.f, 0.f, 0.f);
            if (agrow < NN)
                v = *(const float4*)(A32 + (size_t)agrow * DD + k0 + q * 4);
            __nv_bfloat16 h[4], l[4];
            bf_split(v.x, h[0], l[0]); bf_split(v.y, h[1], l[1]);
            bf_split(v.z, h[2], l[2]); bf_split(v.w, h[3], l[3]);
            uint32_t so = (uint32_t)(row * ROWB + q * 8);
            *(uint2*)(smem + so)         = *(uint2*)h;
            *(uint2*)(smem + TILEB + so) = *(uint2*)l;
        }
        #pragma unroll
        for (int s = 0; s < 2; s++) {
            int idx = tid + s * 256;
            int row = idx >> 2;
            int q   = idx & 3;
            uint32_t so = (uint32_t)(row * ROWB + q * 16);
            const size_t gb = (size_t)(col0 + row) * DD + k0 + q * 8;
            *(float4*)(smem + 2 * TILEB + so) = *(const float4*)(g_wbh + gb);
            *(float4*)(smem + 3 * TILEB + so) = *(const float4*)(g_wbl + gb);
        }
        __syncthreads();

        #pragma unroll
        for (int ks = 0; ks < 2; ks++) {
            uint32_t ao = sb + aob + ks * 32;
            uint32_t bo = sb + bob + ks * 32;
            uint32_t ahi[2][4], alo[2][4];
            #pragma unroll
            for (int mt = 0; mt < 2; mt++) {
                ldx4(ahi[mt], ao + mt * 16 * ROWB);
                ldx4(alo[mt], TILEB + ao + mt * 16 * ROWB);
            }
            #pragma unroll
            for (int nt = 0; nt < 8; nt++) {
                uint32_t bh[2], bl[2];
                ldx2(bh, 2 * TILEB + bo + nt * 8 * ROWB);
                ldx2(bl, 3 * TILEB + bo + nt * 8 * ROWB);
                #pragma unroll
                for (int mt = 0; mt < 2; mt++) {
                    mma16816(acc[mt][nt], ahi[mt], bh);
                    mma16816(acc[mt][nt], ahi[mt], bl);
                    mma16816(acc[mt][nt], alo[mt], bh);
                }
            }
        }
    }

    const int g = lane >> 2, t2 = (lane & 3) * 2;
    #pragma unroll
    for (int mt = 0; mt < 2; mt++) {
        int r = row0 + wm * 32 + mt * 16 + g;
        #pragma unroll
        for (int nt = 0; nt < 8; nt++) {
            int col = col0 + wn * 64 + nt * 8 + t2;
            if (r < NN)
                *(float2*)(C + (size_t)r * DD + col) = make_float2(acc[mt][nt][0], acc[mt][nt][1]);
            if (r + 8 < NN)
                *(float2*)(C + (size_t)(r + 8) * DD + col) = make_float2(acc[mt][nt][2], acc[mt][nt][3]);
        }
    }
}

// score: sq[n] = xq[n] . wa1,  sn[n] = xin[n] . wa2  (exact fp32)
__global__ void score(const float* __restrict__ xq, const float* __restrict__ xin) {
    int node = blockIdx.x;
    int t = threadIdx.x;
    size_t idx = (size_t)node * DD + t;

    float vq = xq[idx]  * g_wa1[t];
    float vn = xin[idx] * g_wa2[t];
    #pragma unroll
    for (int o = 16; o > 0; o >>= 1) {
        vq += __shfl_down_sync(0xFFFFFFFFu, vq, o);
        vn += __shfl_down_sync(0xFFFFFFFFu, vn, o);
    }
    __shared__ float sqs[8], sns[8];
    int w = t >> 5, ln = t & 31;
    if (ln == 0) { sqs[w] = vq; sns[w] = vn; }
    __syncthreads();
    if (t == 0) {
        float S = 0.f, T = 0.f;
        #pragma unroll
        for (int i = 0; i < 8; i++) { S += sqs[i]; T += sns[i]; }
        g_sq[node] = S;
        g_sn[node] = T;
    }
}

// Fused edge-gather + normalize + (residual) write. One block per node.
__global__ void __launch_bounds__(256)
edge_agg(const float* __restrict__ nodes, float* __restrict__ out, int last) {
    __shared__ float ws[256];
    __shared__ int   sdst[256];
    __shared__ float rs_s;

    const int node = blockIdx.x;               // b*NN + n
    const int b = node / NN;
    const int t = threadIdx.x;
    const int off = g_eoff[node], end = g_eoff[node + 1];
    const float sq = g_sq[node];
    const float* __restrict__ hb = g_h + (size_t)b * NN * DD;
    const float* __restrict__ snb = g_sn + b * NN;

    float acc = 0.f, rs = 0.f;

    for (int base = off; base < end; base += 256) {
        int m = min(256, end - base);
        if (t < m) {
            int dst = g_edst[base + t];
            sdst[t] = dst;
            float s = sq + snb[dst];
            float lr = (s >= 0.f) ? s : ALPHA * s;
            ws[t] = __expf(-lr);
        }
        __syncthreads();
        int j = 0;
        for (; j + 4 <= m; j += 4) {
            int d0 = sdst[j], d1 = sdst[j+1], d2 = sdst[j+2], d3 = sdst[j+3];
            float w0 = ws[j], w1 = ws[j+1], w2 = ws[j+2], w3 = ws[j+3];
            float h0 = hb[(size_t)d0 * DD + t];
            float h1 = hb[(size_t)d1 * DD + t];
            float h2 = hb[(size_t)d2 * DD + t];
            float h3 = hb[(size_t)d3 * DD + t];
            acc += w0 * h0 + w1 * h1 + w2 * h2 + w3 * h3;
            rs  += w0 + w1 + w2 + w3;
        }
        for (; j < m; j++) {
            acc += ws[j] * hb[(size_t)sdst[j] * DD + t];
            rs  += ws[j];
        }
        __syncthreads();
    }
    (void)rs_s;

    float v = (rs == 0.f) ? 0.f : acc / rs;
    size_t idx = (size_t)node * DD + t;
    if (last) out[idx] = v + nodes[idx];
    else      g_cur[idx] = v;
}

// ---------------------------------------------------------------------------
extern "C" void kernel_launch(void* const* d_in, const int* in_sizes, int n_in,
                              void* d_out, int out_size) {
    const float* nodes  = (const float*)d_in[0];
    const float* nodesq = (const float*)d_in[1];
    const float* W      = (const float*)d_in[2];
    const float* a      = (const float*)d_in[3];
    const int*   edges  = (const int*)d_in[4];
    float* out = (float*)d_out;

    // ---- CSR build (edges launch-invariant; rebuilt every call) ----
    zero_deg<<<(NNODES + 255) / 256, 256>>>();
    hist<<<(NEDGES + 255) / 256, 256>>>(edges);
    scan_deg<<<1, 1024>>>();
    copy_cur<<<(NNODES + 255) / 256, 256>>>();
    scatter<<<(NEDGES + 255) / 256, 256>>>(edges);

    float* curp = nullptr;
    cudaGetSymbolAddress((void**)&curp, g_cur);

    dim3 ggrid(NTILES, DD / TN, NB);

    for (int l = 0; l < NL; l++) {
        const float* Wl  = W + (size_t)l * DD * DD;
        const float* xin = (l == 0) ? nodes : curp;
        wa_kernel<<<DD, DD>>>(Wl, a + (size_t)l * 2 * DD);
        prep_w<<<DD, DD>>>(Wl);
        gemm_mma<<<ggrid, 256, SMEMB>>>(xin);
        score<<<NNODES, 256>>>(nodesq, xin);
        edge_agg<<<NNODES, 256>>>(nodes, out, l == NL - 1);
    }
}

// round 8
// speedup vs baseline: 2.4503x; 1.1676x over previous
#include <cuda_runtime.h>
#include <cuda_bf16.h>
#include <cstdint>

#define NB 2
#define NN 20000
#define DD 256
#define EE 320000
#define NL 2
#define ALPHA 0.2f

#define TM 128
#define TN 128
#define KC 32
#define NST (DD / KC)                 // 8
#define NTILES ((NN + TM - 1) / TM)   // 157
#define ROWB 80                       // 64B data + 16B pad
#define TILEB (128 * ROWB)            // 10240
#define STAGEB (4 * TILEB)            // 40960
#define SMEMB (2 * STAGEB)            // 81920 (2-stage)
#define NNODES (NB * NN)              // 40000
#define NEDGES (NB * EE)              // 640000

// ---------------- device scratch ----------------
__device__ float g_h[NB * NN * DD];
__device__ float g_sqL[2 * NNODES];          // sq per layer
__device__ float g_snA[NNODES], g_snB[NNODES];
__device__ float g_wa1[2 * DD], g_wa2[2 * DD];
__device__ __nv_bfloat16 g_ah[NB * NN * DD], g_al[NB * NN * DD];  // activation hi/lo
__device__ __nv_bfloat16 g_wbh[2 * DD * DD], g_wbl[2 * DD * DD];  // W^T hi/lo per layer
// CSR
__device__ int g_deg [NNODES];
__device__ int g_eoff[NNODES + 1];
__device__ int g_ecur[NNODES];
__device__ int g_edst[NEDGES];

// ---------------- helpers ----------------
__device__ __forceinline__ uint32_t smem_u32(const void* p) {
    uint32_t a;
    asm("{ .reg .u64 t; cvta.to.shared.u64 t, %1; cvt.u32.u64 %0, t; }" : "=r"(a) : "l"(p));
    return a;
}
__device__ __forceinline__ void bf_split(float v, __nv_bfloat16& hi, __nv_bfloat16& lo) {
    hi = __float2bfloat16_rn(v);
    lo = __float2bfloat16_rn(v - __bfloat162float(hi));
}
__device__ __forceinline__ void cp16(uint32_t dst, const void* src, int bytes) {
    asm volatile("cp.async.cg.shared.global [%0], [%1], 16, %2;"
                 :: "r"(dst), "l"(src), "r"(bytes) : "memory");
}
#define CP_COMMIT() asm volatile("cp.async.commit_group;" ::: "memory")
#define CP_WAIT(n)  asm volatile("cp.async.wait_group %0;" :: "n"(n) : "memory")
__device__ __forceinline__ void ldx4(uint32_t r[4], uint32_t addr) {
    asm volatile("ldmatrix.sync.aligned.m8n8.x4.shared.b16 {%0,%1,%2,%3}, [%4];"
                 : "=r"(r[0]), "=r"(r[1]), "=r"(r[2]), "=r"(r[3]) : "r"(addr));
}
__device__ __forceinline__ void ldx2(uint32_t r[2], uint32_t addr) {
    asm volatile("ldmatrix.sync.aligned.m8n8.x2.shared.b16 {%0,%1}, [%2];"
                 : "=r"(r[0]), "=r"(r[1]) : "r"(addr));
}
__device__ __forceinline__ void mma16816(float c[4], const uint32_t a[4], const uint32_t b[2]) {
    asm volatile("mma.sync.aligned.m16n8k16.row.col.f32.bf16.bf16.f32 "
                 "{%0,%1,%2,%3}, {%4,%5,%6,%7}, {%8,%9}, {%0,%1,%2,%3};"
                 : "+f"(c[0]), "+f"(c[1]), "+f"(c[2]), "+f"(c[3])
                 : "r"(a[0]), "r"(a[1]), "r"(a[2]), "r"(a[3]), "r"(b[0]), "r"(b[1]));
}

// ============================ CSR construction ============================
__global__ void zero_deg() {
    int i = blockIdx.x * blockDim.x + threadIdx.x;
    if (i < NNODES) g_deg[i] = 0;
}
__global__ void hist(const int* __restrict__ edges) {
    int i = blockIdx.x * blockDim.x + threadIdx.x;
    if (i >= NEDGES) return;
    int b = i / EE, e = i - b * EE;
    int src = edges[(size_t)b * 2 * EE + e];
    atomicAdd(&g_deg[b * NN + src], 1);
}
// 1 block, 1024 threads: 40 serial elems/thread + one block scan
__global__ void scan_deg() {
    __shared__ int s[1024];
    const int per = (NNODES + 1023) / 1024;   // 40
    int base = threadIdx.x * per;
    int loc[40];
    int run = 0;
    #pragma unroll
    for (int j = 0; j < 40; j++) {
        int i = base + j;
        int d = (i < NNODES) ? g_deg[i] : 0;
        run += d;
        loc[j] = run;
    }
    s[threadIdx.x] = run;
    __syncthreads();
    for (int o = 1; o < 1024; o <<= 1) {
        int add = (threadIdx.x >= o) ? s[threadIdx.x - o] : 0;
        __syncthreads();
        s[threadIdx.x] += add;
        __syncthreads();
    }
    int excl = threadIdx.x ? s[threadIdx.x - 1] : 0;
    #pragma unroll
    for (int j = 0; j < 40; j++) {
        int i = base + j;
        if (i < NNODES) g_eoff[i + 1] = excl + loc[j];
    }
    if (threadIdx.x == 0) g_eoff[0] = 0;
}
__global__ void copy_cur() {
    int i = blockIdx.x * blockDim.x + threadIdx.x;
    if (i < NNODES) g_ecur[i] = g_eoff[i];
}
__global__ void scatter(const int* __restrict__ edges) {
    int i = blockIdx.x * blockDim.x + threadIdx.x;
    if (i >= NEDGES) return;
    int b = i / EE, e = i - b * EE;
    const int* eb = edges + (size_t)b * 2 * EE;
    int src = eb[e], dst = eb[EE + e];
    int pos = atomicAdd(&g_ecur[b * NN + src], 1);
    g_edst[pos] = dst;
}

// ============================ prep kernels ============================
__global__ void conv_pair(const float* __restrict__ src) {
    int i = (blockIdx.x * blockDim.x + threadIdx.x) * 4;
    if (i >= NB * NN * DD) return;
    float4 v = *(const float4*)(src + i);
    __nv_bfloat16 h[4], l[4];
    bf_split(v.x, h[0], l[0]); bf_split(v.y, h[1], l[1]);
    bf_split(v.z, h[2], l[2]); bf_split(v.w, h[3], l[3]);
    *(uint2*)(g_ah + i) = *(uint2*)h;
    *(uint2*)(g_al + i) = *(uint2*)l;
}

// wa for both layers: grid (DD, 2)
__global__ void wa_all(const float* __restrict__ W, const float* __restrict__ a) {
    int k = blockIdx.x, l = blockIdx.y, t = threadIdx.x;
    const float* Wl = W + (size_t)l * DD * DD;
    const float* al = a + (size_t)l * 2 * DD;
    float w = Wl[k * DD + t];
    float v1 = w * al[t];
    float v2 = w * al[DD + t];
    #pragma unroll
    for (int o = 16; o > 0; o >>= 1) {
        v1 += __shfl_down_sync(0xFFFFFFFFu, v1, o);
        v2 += __shfl_down_sync(0xFFFFFFFFu, v2, o);
    }
    __shared__ float s1[8], s2[8];
    int wp = t >> 5, ln = t & 31;
    if (ln == 0) { s1[wp] = v1; s2[wp] = v2; }
    __syncthreads();
    if (t == 0) {
        float a1 = 0.f, a2 = 0.f;
        #pragma unroll
        for (int i = 0; i < 8; i++) { a1 += s1[i]; a2 += s2[i]; }
        g_wa1[l * DD + k] = a1;
        g_wa2[l * DD + k] = a2;
    }
}

// prep W^T hi/lo for both layers: grid (DD, 2), block DD
__global__ void prep_w(const float* __restrict__ W) {
    int n = blockIdx.x, l = blockIdx.y, k = threadIdx.x;
    float v = W[(size_t)l * DD * DD + k * DD + n];
    __nv_bfloat16 h, lo;
    bf_split(v, h, lo);
    g_wbh[(size_t)l * DD * DD + n * DD + k] = h;
    g_wbl[(size_t)l * DD * DD + n * DD + k] = lo;
}

// score_all: sq(l0), sq(l1) from xq; sn(l0) from nodes. One 41MB sweep.
__global__ void score_all(const float* __restrict__ xq, const float* __restrict__ x0) {
    int node = blockIdx.x;
    int t = threadIdx.x;
    size_t idx = (size_t)node * DD + t;
    float q = xq[idx], x = x0[idx];
    float v0 = q * g_wa1[t];
    float v1 = q * g_wa1[DD + t];
    float v2 = x * g_wa2[t];
    #pragma unroll
    for (int o = 16; o > 0; o >>= 1) {
        v0 += __shfl_down_sync(0xFFFFFFFFu, v0, o);
        v1 += __shfl_down_sync(0xFFFFFFFFu, v1, o);
        v2 += __shfl_down_sync(0xFFFFFFFFu, v2, o);
    }
    __shared__ float s0[8], s1[8], s2[8];
    int w = t >> 5, ln = t & 31;
    if (ln == 0) { s0[w] = v0; s1[w] = v1; s2[w] = v2; }
    __syncthreads();
    if (t == 0) {
        float a0 = 0.f, a1 = 0.f, a2 = 0.f;
        #pragma unroll
        for (int i = 0; i < 8; i++) { a0 += s0[i]; a1 += s1[i]; a2 += s2[i]; }
        g_sqL[node] = a0;
        g_sqL[NNODES + node] = a1;
        g_snA[node] = a2;
    }
}

// ============================ GEMM (cp.async, 2-stage) ============================
__global__ void __launch_bounds__(256, 2)
gemm_mma(int layer) {
    extern __shared__ char smem[];
    const int tid = threadIdx.x;
    const int wid = tid >> 5, lane = tid & 31;
    const int wm = wid & 3, wn = wid >> 2;

    const int b = blockIdx.z;
    const size_t boff = (size_t)b * NN * DD;
    const __nv_bfloat16* Ahi = g_ah + boff;
    const __nv_bfloat16* Alo = g_al + boff;
    const __nv_bfloat16* Bhi = g_wbh + (size_t)layer * DD * DD;
    const __nv_bfloat16* Blo = g_wbl + (size_t)layer * DD * DD;
    float* C = g_h + boff;
    const int row0 = blockIdx.x * TM;
    const int col0 = blockIdx.y * TN;

    const uint32_t sb = smem_u32(smem);

    // copy geometry: 512 chunks of 16B per tile, 2 per thread per tile
    const int crow0 = tid >> 2, cq0 = tid & 3;              // chunks 0..255
    const int crow1 = (tid + 256) >> 2, cq1 = tid & 3;      // chunks 256..511
    const int aok0 = (row0 + crow0) < NN ? 16 : 0;
    const int aok1 = (row0 + crow1) < NN ? 16 : 0;
    const uint32_t so0 = (uint32_t)(crow0 * ROWB + cq0 * 16);
    const uint32_t so1 = (uint32_t)(crow1 * ROWB + cq1 * 16);
    const size_t sa0 = (size_t)(row0 + crow0) * DD + cq0 * 8;
    const size_t sa1 = (size_t)(row0 + crow1) * DD + cq1 * 8;
    const size_t sb0 = (size_t)(col0 + crow0) * DD + cq0 * 8;
    const size_t sb1 = (size_t)(col0 + crow1) * DD + cq1 * 8;

    auto issue = [&](int c) {
        uint32_t st = sb + (uint32_t)(c & 1) * STAGEB;
        int k0 = c * KC;
        cp16(st + so0,             Ahi + sa0 + k0, aok0);
        cp16(st + so1,             Ahi + sa1 + k0, aok1);
        cp16(st + TILEB + so0,     Alo + sa0 + k0, aok0);
        cp16(st + TILEB + so1,     Alo + sa1 + k0, aok1);
        cp16(st + 2 * TILEB + so0, Bhi + sb0 + k0, 16);
        cp16(st + 2 * TILEB + so1, Bhi + sb1 + k0, 16);
        cp16(st + 3 * TILEB + so0, Blo + sb0 + k0, 16);
        cp16(st + 3 * TILEB + so1, Blo + sb1 + k0, 16);
        CP_COMMIT();
    };

    float acc[2][8][4];
    #pragma unroll
    for (int i = 0; i < 2; i++)
        #pragma unroll
        for (int j = 0; j < 8; j++)
            #pragma unroll
            for (int q = 0; q < 4; q++) acc[i][j][q] = 0.f;

    const uint32_t aob = (uint32_t)((wm * 32 + (lane & 15)) * ROWB + (lane >> 4) * 16);
    const uint32_t bob = (uint32_t)((wn * 64 + (lane & 7)) * ROWB + ((lane >> 3) & 1) * 16);

    issue(0);
    for (int c = 0; c < NST; c++) {
        if (c + 1 < NST) { issue(c + 1); CP_WAIT(1); }
        else             { CP_WAIT(0); }
        __syncthreads();

        uint32_t st = sb + (uint32_t)(c & 1) * STAGEB;
        #pragma unroll
        for (int ks = 0; ks < 2; ks++) {
            uint32_t ao = st + aob + ks * 32;
            uint32_t bo = st + bob + ks * 32;
            uint32_t ahi[2][4], alo[2][4];
            #pragma unroll
            for (int mt = 0; mt < 2; mt++) {
                ldx4(ahi[mt], ao + mt * 16 * ROWB);
                ldx4(alo[mt], TILEB + ao + mt * 16 * ROWB);
            }
            #pragma unroll
            for (int nt = 0; nt < 8; nt++) {
                uint32_t bh[2], bl[2];
                ldx2(bh, 2 * TILEB + bo + nt * 8 * ROWB);
                ldx2(bl, 3 * TILEB + bo + nt * 8 * ROWB);
                #pragma unroll
                for (int mt = 0; mt < 2; mt++) {
                    mma16816(acc[mt][nt], ahi[mt], bh);
                    mma16816(acc[mt][nt], ahi[mt], bl);
                    mma16816(acc[mt][nt], alo[mt], bh);
                }
            }
        }
        __syncthreads();
    }

    const int g = lane >> 2, t2 = (lane & 3) * 2;
    #pragma unroll
    for (int mt = 0; mt < 2; mt++) {
        int r = row0 + wm * 32 + mt * 16 + g;
        #pragma unroll
        for (int nt = 0; nt < 8; nt++) {
            int col = col0 + wn * 64 + nt * 8 + t2;
            if (r < NN)
                *(float2*)(C + (size_t)r * DD + col) = make_float2(acc[mt][nt][0], acc[mt][nt][1]);
            if (r + 8 < NN)
                *(float2*)(C + (size_t)(r + 8) * DD + col) = make_float2(acc[mt][nt][2], acc[mt][nt][3]);
        }
    }
}

// ============================ fused edge aggregate ============================
// One block per node. Gathers, normalizes, then either:
//   last=0: writes bf16 hi/lo next-layer input AND sn_next = v . wa2_next
//   last=1: writes out = v + nodes
__global__ void __launch_bounds__(256)
edge_agg(const float* __restrict__ nodes, float* __restrict__ out,
         const float* __restrict__ sqp, const float* __restrict__ snp,
         float* __restrict__ sn_out, const float* __restrict__ wa2n, int last) {
    __shared__ float ws[256];
    __shared__ int   sdst[256];
    __shared__ float red[8];

    const int node = blockIdx.x;
    const int b = node / NN;
    const int t = threadIdx.x;
    const int off = g_eoff[node], end = g_eoff[node + 1];
    const float sq = sqp[node];
    const float* __restrict__ hb = g_h + (size_t)b * NN * DD;
    const float* __restrict__ snb = snp + b * NN;

    float acc = 0.f, rs = 0.f;

    for (int base = off; base < end; base += 256) {
        int m = min(256, end - base);
        if (t < m) {
            int dst = g_edst[base + t];
            sdst[t] = dst;
            float s = sq + snb[dst];
            float lr = (s >= 0.f) ? s : ALPHA * s;
            ws[t] = __expf(-lr);
        }
        __syncthreads();
        int j = 0;
        for (; j + 4 <= m; j += 4) {
            int d0 = sdst[j], d1 = sdst[j+1], d2 = sdst[j+2], d3 = sdst[j+3];
            float w0 = ws[j], w1 = ws[j+1], w2 = ws[j+2], w3 = ws[j+3];
            acc += w0 * hb[(size_t)d0 * DD + t] + w1 * hb[(size_t)d1 * DD + t]
                 + w2 * hb[(size_t)d2 * DD + t] + w3 * hb[(size_t)d3 * DD + t];
            rs  += w0 + w1 + w2 + w3;
        }
        for (; j < m; j++) {
            acc += ws[j] * hb[(size_t)sdst[j] * DD + t];
            rs  += ws[j];
        }
        __syncthreads();
    }

    float v = (rs == 0.f) ? 0.f : acc / rs;
    size_t idx = (size_t)node * DD + t;

    if (last) {
        out[idx] = v + nodes[idx];
    } else {
        __nv_bfloat16 h, l;
        bf_split(v, h, l);
        g_ah[idx] = h;
        g_al[idx] = l;
        // sn_next[node] = v . wa2_next
        float p = v * wa2n[t];
        #pragma unroll
        for (int o = 16; o > 0; o >>= 1)
            p += __shfl_down_sync(0xFFFFFFFFu, p, o);
        int w = t >> 5, ln = t & 31;
        if (ln == 0) red[w] = p;
        __syncthreads();
        if (t == 0) {
            float S = 0.f;
            #pragma unroll
            for (int i = 0; i < 8; i++) S += red[i];
            sn_out[node] = S;
        }
    }
}

// ---------------------------------------------------------------------------
extern "C" void kernel_launch(void* const* d_in, const int* in_sizes, int n_in,
                              void* d_out, int out_size) {
    const float* nodes  = (const float*)d_in[0];
    const float* nodesq = (const float*)d_in[1];
    const float* W      = (const float*)d_in[2];
    const float* a      = (const float*)d_in[3];
    const int*   edges  = (const int*)d_in[4];
    float* out = (float*)d_out;

    cudaFuncSetAttribute(gemm_mma, cudaFuncAttributeMaxDynamicSharedMemorySize, SMEMB);

    // CSR build
    zero_deg<<<(NNODES + 255) / 256, 256>>>();
    hist<<<(NEDGES + 255) / 256, 256>>>(edges);
    scan_deg<<<1, 1024>>>();
    copy_cur<<<(NNODES + 255) / 256, 256>>>();
    scatter<<<(NEDGES + 255) / 256, 256>>>(edges);

    // Operand prep
    conv_pair<<<(NB * NN * DD / 4 + 255) / 256, 256>>>(nodes);
    wa_all<<<dim3(DD, 2), 256>>>(W, a);
    prep_w<<<dim3(DD, 2), DD>>>(W);
    score_all<<<NNODES, 256>>>(nodesq, nodes);

    float *sqL = nullptr, *snA = nullptr, *snB = nullptr, *wa2 = nullptr;
    cudaGetSymbolAddress((void**)&sqL, g_sqL);
    cudaGetSymbolAddress((void**)&snA, g_snA);
    cudaGetSymbolAddress((void**)&snB, g_snB);
    cudaGetSymbolAddress((void**)&wa2, g_wa2);

    dim3 ggrid(NTILES, DD / TN, NB);

    // layer 0
    gemm_mma<<<ggrid, 256, SMEMB>>>(0);
    edge_agg<<<NNODES, 256>>>(nodes, out, sqL, snA, snB, wa2 + DD, 0);
    // layer 1
    gemm_mma<<<ggrid, 256, SMEMB>>>(1);
    edge_agg<<<NNODES, 256>>>(nodes, out, sqL + NNODES, snB, nullptr, nullptr, 1);
}

// round 9
// speedup vs baseline: 2.6942x; 1.0995x over previous
#include <cuda_runtime.h>
#include <cuda_bf16.h>
#include <cstdint>

#define NB 2
#define NN 20000
#define DD 256
#define EE 320000
#define NL 2
#define ALPHA 0.2f

#define TM 128
#define TN 128
#define KC 32
#define NST (DD / KC)                 // 8
#define NTILES ((NN + TM - 1) / TM)   // 157
#define ROWB 80                       // 64B data + 16B pad
#define TILEB (128 * ROWB)            // 10240
#define STAGEB (4 * TILEB)            // 40960
#define SMEMB (2 * STAGEB)            // 81920 (2-stage)
#define NNODES (NB * NN)              // 40000
#define NEDGES (NB * EE)              // 640000

// ---------------- device scratch ----------------
__device__ float g_h[NB * NN * DD];
__device__ float g_sqL[2 * NNODES];
__device__ float g_snA[NNODES], g_snB[NNODES];
__device__ float g_wa1[2 * DD], g_wa2[2 * DD];
__device__ __nv_bfloat16 g_ah[NB * NN * DD], g_al[NB * NN * DD];
__device__ __nv_bfloat16 g_wbh[2 * DD * DD], g_wbl[2 * DD * DD];
// CSR
__device__ int g_deg [NNODES];
__device__ int g_eoff[NNODES + 1];
__device__ int g_ecur[NNODES];
__device__ int g_edst[NEDGES];

// ---------------- helpers ----------------
__device__ __forceinline__ uint32_t smem_u32(const void* p) {
    uint32_t a;
    asm("{ .reg .u64 t; cvta.to.shared.u64 t, %1; cvt.u32.u64 %0, t; }" : "=r"(a) : "l"(p));
    return a;
}
__device__ __forceinline__ void bf_split(float v, __nv_bfloat16& hi, __nv_bfloat16& lo) {
    hi = __float2bfloat16_rn(v);
    lo = __float2bfloat16_rn(v - __bfloat162float(hi));
}
__device__ __forceinline__ void cp16(uint32_t dst, const void* src, int bytes) {
    asm volatile("cp.async.cg.shared.global [%0], [%1], 16, %2;"
                 :: "r"(dst), "l"(src), "r"(bytes) : "memory");
}
#define CP_COMMIT() asm volatile("cp.async.commit_group;" ::: "memory")
#define CP_WAIT(n)  asm volatile("cp.async.wait_group %0;" :: "n"(n) : "memory")
__device__ __forceinline__ void ldx4(uint32_t r[4], uint32_t addr) {
    asm volatile("ldmatrix.sync.aligned.m8n8.x4.shared.b16 {%0,%1,%2,%3}, [%4];"
                 : "=r"(r[0]), "=r"(r[1]), "=r"(r[2]), "=r"(r[3]) : "r"(addr));
}
__device__ __forceinline__ void ldx2(uint32_t r[2], uint32_t addr) {
    asm volatile("ldmatrix.sync.aligned.m8n8.x2.shared.b16 {%0,%1}, [%2];"
                 : "=r"(r[0]), "=r"(r[1]) : "r"(addr));
}
__device__ __forceinline__ void mma16816(float c[4], const uint32_t a[4], const uint32_t b[2]) {
    asm volatile("mma.sync.aligned.m16n8k16.row.col.f32.bf16.bf16.f32 "
                 "{%0,%1,%2,%3}, {%4,%5,%6,%7}, {%8,%9}, {%0,%1,%2,%3};"
                 : "+f"(c[0]), "+f"(c[1]), "+f"(c[2]), "+f"(c[3])
                 : "r"(a[0]), "r"(a[1]), "r"(a[2]), "r"(a[3]), "r"(b[0]), "r"(b[1]));
}

// ============================ CSR construction ============================
__global__ void hist(const int* __restrict__ edges) {
    int i = blockIdx.x * blockDim.x + threadIdx.x;
    if (i >= NEDGES) return;
    int b = i / EE, e = i - b * EE;
    int src = edges[(size_t)b * 2 * EE + e];
    atomicAdd(&g_deg[b * NN + src], 1);
}
// 1 block, 1024 threads: 40 serial elems/thread + one block scan.
// Emits exclusive offsets g_eoff AND the scatter cursor g_ecur.
__global__ void scan_deg() {
    __shared__ int s[1024];
    const int base = threadIdx.x * 40;
    int loc[40];
    int run = 0;
    #pragma unroll
    for (int j = 0; j < 40; j++) {
        int i = base + j;
        int d = (i < NNODES) ? g_deg[i] : 0;
        run += d;
        loc[j] = run;
    }
    s[threadIdx.x] = run;
    __syncthreads();
    for (int o = 1; o < 1024; o <<= 1) {
        int add = (threadIdx.x >= o) ? s[threadIdx.x - o] : 0;
        __syncthreads();
        s[threadIdx.x] += add;
        __syncthreads();
    }
    int excl = threadIdx.x ? s[threadIdx.x - 1] : 0;
    int prev = excl;
    #pragma unroll
    for (int j = 0; j < 40; j++) {
        int i = base + j;
        if (i < NNODES) {
            g_ecur[i] = prev;
            g_eoff[i + 1] = excl + loc[j];
            prev = excl + loc[j];
        }
    }
    if (threadIdx.x == 0) g_eoff[0] = 0;
}
__global__ void scatter(const int* __restrict__ edges) {
    int i = blockIdx.x * blockDim.x + threadIdx.x;
    if (i >= NEDGES) return;
    int b = i / EE, e = i - b * EE;
    const int* eb = edges + (size_t)b * 2 * EE;
    int src = eb[e], dst = eb[EE + e];
    int pos = atomicAdd(&g_ecur[b * NN + src], 1);
    g_edst[pos] = dst;
}

// ============================ prep kernels ============================
__global__ void conv_pair(const float* __restrict__ src) {
    int i = (blockIdx.x * blockDim.x + threadIdx.x) * 4;
    if (i >= NB * NN * DD) return;
    float4 v = *(const float4*)(src + i);
    __nv_bfloat16 h[4], l[4];
    bf_split(v.x, h[0], l[0]); bf_split(v.y, h[1], l[1]);
    bf_split(v.z, h[2], l[2]); bf_split(v.w, h[3], l[3]);
    *(uint2*)(g_ah + i) = *(uint2*)h;
    *(uint2*)(g_al + i) = *(uint2*)l;
}

__global__ void wa_all(const float* __restrict__ W, const float* __restrict__ a) {
    int k = blockIdx.x, l = blockIdx.y, t = threadIdx.x;
    const float* Wl = W + (size_t)l * DD * DD;
    const float* al = a + (size_t)l * 2 * DD;
    float w = Wl[k * DD + t];
    float v1 = w * al[t];
    float v2 = w * al[DD + t];
    #pragma unroll
    for (int o = 16; o > 0; o >>= 1) {
        v1 += __shfl_down_sync(0xFFFFFFFFu, v1, o);
        v2 += __shfl_down_sync(0xFFFFFFFFu, v2, o);
    }
    __shared__ float s1[8], s2[8];
    int wp = t >> 5, ln = t & 31;
    if (ln == 0) { s1[wp] = v1; s2[wp] = v2; }
    __syncthreads();
    if (t == 0) {
        float a1 = 0.f, a2 = 0.f;
        #pragma unroll
        for (int i = 0; i < 8; i++) { a1 += s1[i]; a2 += s2[i]; }
        g_wa1[l * DD + k] = a1;
        g_wa2[l * DD + k] = a2;
    }
}

__global__ void prep_w(const float* __restrict__ W) {
    int n = blockIdx.x, l = blockIdx.y, k = threadIdx.x;
    float v = W[(size_t)l * DD * DD + k * DD + n];
    __nv_bfloat16 h, lo;
    bf_split(v, h, lo);
    g_wbh[(size_t)l * DD * DD + n * DD + k] = h;
    g_wbl[(size_t)l * DD * DD + n * DD + k] = lo;
}

__global__ void score_all(const float* __restrict__ xq, const float* __restrict__ x0) {
    int node = blockIdx.x;
    int t = threadIdx.x;
    size_t idx = (size_t)node * DD + t;
    float q = xq[idx], x = x0[idx];
    float v0 = q * g_wa1[t];
    float v1 = q * g_wa1[DD + t];
    float v2 = x * g_wa2[t];
    #pragma unroll
    for (int o = 16; o > 0; o >>= 1) {
        v0 += __shfl_down_sync(0xFFFFFFFFu, v0, o);
        v1 += __shfl_down_sync(0xFFFFFFFFu, v1, o);
        v2 += __shfl_down_sync(0xFFFFFFFFu, v2, o);
    }
    __shared__ float s0[8], s1[8], s2[8];
    int w = t >> 5, ln = t & 31;
    if (ln == 0) { s0[w] = v0; s1[w] = v1; s2[w] = v2; }
    __syncthreads();
    if (t == 0) {
        float a0 = 0.f, a1 = 0.f, a2 = 0.f;
        #pragma unroll
        for (int i = 0; i < 8; i++) { a0 += s0[i]; a1 += s1[i]; a2 += s2[i]; }
        g_sqL[node] = a0;
        g_sqL[NNODES + node] = a1;
        g_snA[node] = a2;
    }
}

// ============================ GEMM (cp.async, 2-stage) ============================
__global__ void __launch_bounds__(256, 2)
gemm_mma(int layer) {
    extern __shared__ char smem[];
    const int tid = threadIdx.x;
    const int wid = tid >> 5, lane = tid & 31;
    const int wm = wid & 3, wn = wid >> 2;

    const int b = blockIdx.z;
    const size_t boff = (size_t)b * NN * DD;
    const __nv_bfloat16* Ahi = g_ah + boff;
    const __nv_bfloat16* Alo = g_al + boff;
    const __nv_bfloat16* Bhi = g_wbh + (size_t)layer * DD * DD;
    const __nv_bfloat16* Blo = g_wbl + (size_t)layer * DD * DD;
    float* C = g_h + boff;
    const int row0 = blockIdx.x * TM;
    const int col0 = blockIdx.y * TN;

    const uint32_t sb = smem_u32(smem);

    const int crow0 = tid >> 2, cq0 = tid & 3;
    const int crow1 = (tid + 256) >> 2, cq1 = tid & 3;
    const int aok0 = (row0 + crow0) < NN ? 16 : 0;
    const int aok1 = (row0 + crow1) < NN ? 16 : 0;
    const uint32_t so0 = (uint32_t)(crow0 * ROWB + cq0 * 16);
    const uint32_t so1 = (uint32_t)(crow1 * ROWB + cq1 * 16);
    const size_t sa0 = (size_t)(row0 + crow0) * DD + cq0 * 8;
    const size_t sa1 = (size_t)(row0 + crow1) * DD + cq1 * 8;
    const size_t sb0 = (size_t)(col0 + crow0) * DD + cq0 * 8;
    const size_t sb1 = (size_t)(col0 + crow1) * DD + cq1 * 8;

    auto issue = [&](int c) {
        uint32_t st = sb + (uint32_t)(c & 1) * STAGEB;
        int k0 = c * KC;
        cp16(st + so0,             Ahi + sa0 + k0, aok0);
        cp16(st + so1,             Ahi + sa1 + k0, aok1);
        cp16(st + TILEB + so0,     Alo + sa0 + k0, aok0);
        cp16(st + TILEB + so1,     Alo + sa1 + k0, aok1);
        cp16(st + 2 * TILEB + so0, Bhi + sb0 + k0, 16);
        cp16(st + 2 * TILEB + so1, Bhi + sb1 + k0, 16);
        cp16(st + 3 * TILEB + so0, Blo + sb0 + k0, 16);
        cp16(st + 3 * TILEB + so1, Blo + sb1 + k0, 16);
        CP_COMMIT();
    };

    float acc[2][8][4];
    #pragma unroll
    for (int i = 0; i < 2; i++)
        #pragma unroll
        for (int j = 0; j < 8; j++)
            #pragma unroll
            for (int q = 0; q < 4; q++) acc[i][j][q] = 0.f;

    const uint32_t aob = (uint32_t)((wm * 32 + (lane & 15)) * ROWB + (lane >> 4) * 16);
    const uint32_t bob = (uint32_t)((wn * 64 + (lane & 7)) * ROWB + ((lane >> 3) & 1) * 16);

    issue(0);
    for (int c = 0; c < NST; c++) {
        if (c + 1 < NST) { issue(c + 1); CP_WAIT(1); }
        else             { CP_WAIT(0); }
        __syncthreads();

        uint32_t st = sb + (uint32_t)(c & 1) * STAGEB;
        #pragma unroll
        for (int ks = 0; ks < 2; ks++) {
            uint32_t ao = st + aob + ks * 32;
            uint32_t bo = st + bob + ks * 32;
            uint32_t ahi[2][4], alo[2][4];
            #pragma unroll
            for (int mt = 0; mt < 2; mt++) {
                ldx4(ahi[mt], ao + mt * 16 * ROWB);
                ldx4(alo[mt], TILEB + ao + mt * 16 * ROWB);
            }
            #pragma unroll
            for (int nt = 0; nt < 8; nt++) {
                uint32_t bh[2], bl[2];
                ldx2(bh, 2 * TILEB + bo + nt * 8 * ROWB);
                ldx2(bl, 3 * TILEB + bo + nt * 8 * ROWB);
                #pragma unroll
                for (int mt = 0; mt < 2; mt++) {
                    mma16816(acc[mt][nt], ahi[mt], bh);
                    mma16816(acc[mt][nt], ahi[mt], bl);
                    mma16816(acc[mt][nt], alo[mt], bh);
                }
            }
        }
        __syncthreads();
    }

    const int g = lane >> 2, t2 = (lane & 3) * 2;
    #pragma unroll
    for (int mt = 0; mt < 2; mt++) {
        int r = row0 + wm * 32 + mt * 16 + g;
        #pragma unroll
        for (int nt = 0; nt < 8; nt++) {
            int col = col0 + wn * 64 + nt * 8 + t2;
            if (r < NN)
                *(float2*)(C + (size_t)r * DD + col) = make_float2(acc[mt][nt][0], acc[mt][nt][1]);
            if (r + 8 < NN)
                *(float2*)(C + (size_t)(r + 8) * DD + col) = make_float2(acc[mt][nt][2], acc[mt][nt][3]);
        }
    }
}

// ============================ fused edge aggregate ============================
__global__ void __launch_bounds__(256)
edge_agg(const float* __restrict__ nodes, float* __restrict__ out,
         const float* __restrict__ sqp, const float* __restrict__ snp,
         float* __restrict__ sn_out, const float* __restrict__ wa2n, int last) {
    __shared__ float ws[256];
    __shared__ int   sdst[256];
    __shared__ float red[8];

    const int node = blockIdx.x;
    const int b = node / NN;
    const int t = threadIdx.x;
    const int off = g_eoff[node], end = g_eoff[node + 1];
    const float sq = sqp[node];
    const float* __restrict__ hb = g_h + (size_t)b * NN * DD;
    const float* __restrict__ snb = snp + b * NN;

    float acc = 0.f, rs = 0.f;

    for (int base = off; base < end; base += 256) {
        int m = min(256, end - base);
        if (t < m) {
            int dst = g_edst[base + t];
            sdst[t] = dst;
            float s = sq + snb[dst];
            float lr = (s >= 0.f) ? s : ALPHA * s;
            ws[t] = __expf(-lr);
        }
        __syncthreads();
        int j = 0;
        for (; j + 4 <= m; j += 4) {
            int d0 = sdst[j], d1 = sdst[j+1], d2 = sdst[j+2], d3 = sdst[j+3];
            float w0 = ws[j], w1 = ws[j+1], w2 = ws[j+2], w3 = ws[j+3];
            acc += w0 * hb[(size_t)d0 * DD + t] + w1 * hb[(size_t)d1 * DD + t]
                 + w2 * hb[(size_t)d2 * DD + t] + w3 * hb[(size_t)d3 * DD + t];
            rs  += w0 + w1 + w2 + w3;
        }
        for (; j < m; j++) {
            acc += ws[j] * hb[(size_t)sdst[j] * DD + t];
            rs  += ws[j];
        }
        __syncthreads();
    }

    float v = (rs == 0.f) ? 0.f : acc / rs;
    size_t idx = (size_t)node * DD + t;

    if (last) {
        out[idx] = v + nodes[idx];
    } else {
        __nv_bfloat16 h, l;
        bf_split(v, h, l);
        g_ah[idx] = h;
        g_al[idx] = l;
        float p = v * wa2n[t];
        #pragma unroll
        for (int o = 16; o > 0; o >>= 1)
            p += __shfl_down_sync(0xFFFFFFFFu, p, o);
        int w = t >> 5, ln = t & 31;
        if (ln == 0) red[w] = p;
        __syncthreads();
        if (t == 0) {
            float S = 0.f;
            #pragma unroll
            for (int i = 0; i < 8; i++) S += red[i];
            sn_out[node] = S;
        }
    }
}

// ---------------------------------------------------------------------------
extern "C" void kernel_launch(void* const* d_in, const int* in_sizes, int n_in,
                              void* d_out, int out_size) {
    const float* nodes  = (const float*)d_in[0];
    const float* nodesq = (const float*)d_in[1];
    const float* W      = (const float*)d_in[2];
    const float* a      = (const float*)d_in[3];
    const int*   edges  = (const int*)d_in[4];
    float* out = (float*)d_out;

    // one-time host resources (streams/events only; no device memory)
    static cudaStream_t s1 = nullptr;
    static cudaEvent_t evFork = nullptr, evW = nullptr, evJoin = nullptr;
    if (!s1) {
        cudaStreamCreateWithFlags(&s1, cudaStreamNonBlocking);
        cudaEventCreateWithFlags(&evFork, cudaEventDisableTiming);
        cudaEventCreateWithFlags(&evW,    cudaEventDisableTiming);
        cudaEventCreateWithFlags(&evJoin, cudaEventDisableTiming);
        cudaFuncSetAttribute(gemm_mma, cudaFuncAttributeMaxDynamicSharedMemorySize, SMEMB);
    }

    float *sqL, *snA, *snB, *wa2;
    int* degp;
    cudaGetSymbolAddress((void**)&sqL, g_sqL);
    cudaGetSymbolAddress((void**)&snA, g_snA);
    cudaGetSymbolAddress((void**)&snB, g_snB);
    cudaGetSymbolAddress((void**)&wa2, g_wa2);
    cudaGetSymbolAddress((void**)&degp, g_deg);

    dim3 ggrid(NTILES, DD / TN, NB);

    // ---- fork: side stream builds CSR + scores ----
    cudaEventRecord(evFork, 0);
    cudaStreamWaitEvent(s1, evFork, 0);

    cudaMemsetAsync(degp, 0, NNODES * sizeof(int), s1);
    hist<<<(NEDGES + 255) / 256, 256, 0, s1>>>(edges);
    scan_deg<<<1, 1024, 0, s1>>>();
    scatter<<<(NEDGES + 255) / 256, 256, 0, s1>>>(edges);

    // ---- main stream: operand prep + gemm(l0) ----
    wa_all<<<dim3(DD, 2), 256>>>(W, a);
    cudaEventRecord(evW, 0);
    conv_pair<<<(NB * NN * DD / 4 + 255) / 256, 256>>>(nodes);
    prep_w<<<dim3(DD, 2), DD>>>(W);

    cudaStreamWaitEvent(s1, evW, 0);
    score_all<<<NNODES, 256, 0, s1>>>(nodesq, nodes);
    cudaEventRecord(evJoin, s1);

    gemm_mma<<<ggrid, 256, SMEMB>>>(0);
    cudaStreamWaitEvent(0, evJoin, 0);

    // ---- layers ----
    edge_agg<<<NNODES, 256>>>(nodes, out, sqL, snA, snB, wa2 + DD, 0);
    gemm_mma<<<ggrid, 256, SMEMB>>>(1);
    edge_agg<<<NNODES, 256>>>(nodes, out, sqL + NNODES, snB, nullptr, nullptr, 1);
}